// round 15
// baseline (speedup 1.0000x reference)
#include <cuda_runtime.h>
#include <cuda_fp16.h>

#define NMAX 50176
#define SLOT 128
#define EPS 1e-7f
#define TICKET (NMAX - 1)

__device__ int g_cur[NMAX];                      // [0,n): degrees; [NMAX-1]: ticket
__device__ unsigned int g_sorted[NMAX * SLOT];   // fixed-slot dst buckets
__device__ uint2 g_feat[NMAX * 16];              // fp16 feats (residual output), 4 dims/entry

// ---------------- scatter edges into fixed-slot dst buckets (MLP=8) ----------------
// pack: src in bits [0,17), combo = f0*4+f1 in bits [17,22)
__global__ void k_scatter(const int4* __restrict__ src, const int4* __restrict__ dst,
                          const int4* __restrict__ f0, const int4* __restrict__ f1,
                          int e8, int e) {
    int i = blockIdx.x * blockDim.x + threadIdx.x;
    if (i < e8) {
        int i0 = 2 * i, i1 = 2 * i + 1;
        int4 sA = src[i0], dA = dst[i0], aA = f0[i0], cA = f1[i0];
        int4 sB = src[i1], dB = dst[i1], aB = f0[i1], cB = f1[i1];
        int p0 = atomicAdd(&g_cur[dA.x], 1);
        int p1 = atomicAdd(&g_cur[dA.y], 1);
        int p2 = atomicAdd(&g_cur[dA.z], 1);
        int p3 = atomicAdd(&g_cur[dA.w], 1);
        int p4 = atomicAdd(&g_cur[dB.x], 1);
        int p5 = atomicAdd(&g_cur[dB.y], 1);
        int p6 = atomicAdd(&g_cur[dB.z], 1);
        int p7 = atomicAdd(&g_cur[dB.w], 1);
        if (p0 < SLOT) g_sorted[dA.x * SLOT + p0] = (unsigned)sA.x | ((unsigned)(aA.x * 4 + cA.x) << 17);
        if (p1 < SLOT) g_sorted[dA.y * SLOT + p1] = (unsigned)sA.y | ((unsigned)(aA.y * 4 + cA.y) << 17);
        if (p2 < SLOT) g_sorted[dA.z * SLOT + p2] = (unsigned)sA.z | ((unsigned)(aA.z * 4 + cA.z) << 17);
        if (p3 < SLOT) g_sorted[dA.w * SLOT + p3] = (unsigned)sA.w | ((unsigned)(aA.w * 4 + cA.w) << 17);
        if (p4 < SLOT) g_sorted[dB.x * SLOT + p4] = (unsigned)sB.x | ((unsigned)(aB.x * 4 + cB.x) << 17);
        if (p5 < SLOT) g_sorted[dB.y * SLOT + p5] = (unsigned)sB.y | ((unsigned)(aB.y * 4 + cB.y) << 17);
        if (p6 < SLOT) g_sorted[dB.z * SLOT + p6] = (unsigned)sB.z | ((unsigned)(aB.z * 4 + cB.z) << 17);
        if (p7 < SLOT) g_sorted[dB.w * SLOT + p7] = (unsigned)sB.w | ((unsigned)(aB.w * 4 + cB.w) << 17);
    }
    if (i == 0) {   // tail edges beyond e8*8
        const int* ss = (const int*)src; const int* dd = (const int*)dst;
        const int* aa = (const int*)f0;  const int* cc = (const int*)f1;
        for (int k = e8 * 8; k < e; k++) {
            int p = atomicAdd(&g_cur[dd[k]], 1);
            if (p < SLOT)
                g_sorted[dd[k] * SLOT + p] = (unsigned)ss[k] | ((unsigned)(aa[k] * 4 + cc[k]) << 17);
        }
    }
}

__device__ __forceinline__ __half2 u2h(unsigned u) { return *(__half2*)&u; }

__device__ __forceinline__ void ldsm4(unsigned& r0, unsigned& r1, unsigned& r2, unsigned& r3,
                                      unsigned addr) {
    asm volatile("ldmatrix.sync.aligned.m8n8.x4.shared.b16 {%0,%1,%2,%3}, [%4];"
                 : "=r"(r0), "=r"(r1), "=r"(r2), "=r"(r3) : "r"(addr));
}

__device__ __forceinline__ void mma16816(float& c0, float& c1, float& c2, float& c3,
                                         unsigned a0, unsigned a1, unsigned a2, unsigned a3,
                                         unsigned b0, unsigned b1) {
    asm volatile("mma.sync.aligned.m16n8k16.row.col.f32.f16.f16.f32 "
                 "{%0,%1,%2,%3}, {%4,%5,%6,%7}, {%8,%9}, {%0,%1,%2,%3};"
                 : "+f"(c0), "+f"(c1), "+f"(c2), "+f"(c3)
                 : "r"(a0), "r"(a1), "r"(a2), "r"(a3), "r"(b0), "r"(b1));
}

// one edge (fp32 gather row -> fp16 math), accumulate into sh/mh half2 pairs
#define EDGE_STEP(pj)                                                        \
    do {                                                                     \
        float4 xf = nf4[((pj) & 0x1FFFFu) * 16 + l4];                        \
        uint2 eu = etabu[((pj) >> 17) * 16 + l4];                            \
        __half2 x0 = __floats2half2_rn(xf.x, xf.y);                          \
        __half2 x1 = __floats2half2_rn(xf.z, xf.w);                          \
        __half2 m0 = __hmax2(__hadd2(x0, u2h(eu.x)), zero);                  \
        __half2 m1 = __hmax2(__hadd2(x1, u2h(eu.y)), zero);                  \
        __half2 w0 = h2exp2(__hfma2(m0, bl2h, negC));                        \
        __half2 w1 = h2exp2(__hfma2(m1, bl2h, negC));                        \
        shA = __hadd2(shA, w0); shB = __hadd2(shB, w1);                      \
        mhA = __hfma2(m0, w0, mhA); mhB = __hfma2(m1, w1, mhB);              \
    } while (0)

// ---------------- main: per-warp prefetched tickets, fp32 gather, fp16 math ------
__global__ void __launch_bounds__(256) k_main(
    const float* __restrict__ nf,
    const float* __restrict__ emb0, const float* __restrict__ emb1,
    const float* __restrict__ beta_p, const float* __restrict__ scale_p, int n)
{
    __shared__ __align__(16) uint2 etabu[32 * 16];   // 32 combos x 16 uint2 (4 dims each)

    int t = threadIdx.x;
    for (int idx = t; idx < 32 * 16; idx += 256) {
        int c = idx >> 4, l4i = idx & 15;
        int d = 4 * l4i;
        __half2 h0 = __floats2half2_rn(emb0[(c >> 2) * 64 + d]     + emb1[(c & 3) * 64 + d],
                                       emb0[(c >> 2) * 64 + d + 1] + emb1[(c & 3) * 64 + d + 1]);
        __half2 h1 = __floats2half2_rn(emb0[(c >> 2) * 64 + d + 2] + emb1[(c & 3) * 64 + d + 2],
                                       emb0[(c >> 2) * 64 + d + 3] + emb1[(c & 3) * 64 + d + 3]);
        uint2 o; o.x = *(unsigned*)&h0; o.y = *(unsigned*)&h1;
        etabu[idx] = o;
    }
    __syncthreads();

    int lane = t & 31;
    int half = lane >> 4, l4 = lane & 15;
    float bl2f  = beta_p[0] * 1.4426950408889634f;
    float scale = scale_p[0];
    __half2 bl2h = __float2half2_rn(bl2f);
    __half2 negC = __float2half2_rn(-6.0f);          // softmax log2-shift (invariant)
    __half2 zero = __float2half2_rn(0.0f);
    const float4* nf4 = (const float4*)nf;

    int ntasks = (n + 3) >> 2;                       // 4-node tasks, warp granularity

    int tk;
    if (lane == 0) tk = atomicAdd(&g_cur[TICKET], 1);
    tk = __shfl_sync(0xffffffffu, tk, 0);

    while (tk < ntasks) {
        int tk_next;
        if (lane == 0) tk_next = atomicAdd(&g_cur[TICKET], 1);  // prefetch next ticket
        int nbase = tk * 4;

        #pragma unroll 1
        for (int q = 0; q < 4; q++) {
            int node = nbase + q;
            if (node >= n) break;
            int deg = g_cur[node];
            deg = deg < SLOT ? deg : SLOT;
            int start = node * SLOT;

            float s0 = 0.f, s1 = 0.f, s2 = 0.f, s3 = 0.f;
            float a0 = 0.f, a1 = 0.f, a2 = 0.f, a3 = 0.f;

            #pragma unroll 1
            for (int base = 0; base < deg; base += 32) {
                int cn = deg - base; if (cn > 32) cn = 32;
                unsigned p = g_sorted[start + base + lane];
                int npair = cn >> 1;
                __half2 shA = zero, shB = zero, mhA = zero, mhB = zero;
                int gg = 0;
                #pragma unroll 1
                for (; gg + 8 <= npair; gg += 8) {   // 8 pairs = 16 edges
                    #pragma unroll
                    for (int k = 0; k < 8; k++) {
                        unsigned pj = __shfl_sync(0xffffffffu, p, 2 * (gg + k) + half);
                        EDGE_STEP(pj);
                    }
                }
                if (gg + 4 <= npair) {               // 4-pair group
                    #pragma unroll
                    for (int k = 0; k < 4; k++) {
                        unsigned pj = __shfl_sync(0xffffffffu, p, 2 * (gg + k) + half);
                        EDGE_STEP(pj);
                    }
                    gg += 4;
                }
                #pragma unroll 1
                for (; gg < npair; gg++) {           // leftover pairs
                    unsigned pj = __shfl_sync(0xffffffffu, p, 2 * gg + half);
                    EDGE_STEP(pj);
                }
                if (cn & 1) {                        // odd tail edge: half 0 only
                    unsigned pj = __shfl_sync(0xffffffffu, p, cn - 1);
                    if (half == 0) EDGE_STEP(pj);
                }
                // one fp32 dump per 32-edge chunk (bounded: <=16 edges x 2^8.5 << 65504)
                float2 fsA = __half22float2(shA), fsB = __half22float2(shB);
                float2 fmA = __half22float2(mhA), fmB = __half22float2(mhB);
                s0 += fsA.x; s1 += fsA.y; s2 += fsB.x; s3 += fsB.y;
                a0 += fmA.x; a1 += fmA.y; a2 += fmB.x; a3 += fmB.y;
            }

            // fold the two half-warps
            s0 += __shfl_xor_sync(0xffffffffu, s0, 16);
            s1 += __shfl_xor_sync(0xffffffffu, s1, 16);
            s2 += __shfl_xor_sync(0xffffffffu, s2, 16);
            s3 += __shfl_xor_sync(0xffffffffu, s3, 16);
            a0 += __shfl_xor_sync(0xffffffffu, a0, 16);
            a1 += __shfl_xor_sync(0xffffffffu, a1, 16);
            a2 += __shfl_xor_sync(0xffffffffu, a2, 16);
            a3 += __shfl_xor_sync(0xffffffffu, a3, 16);

            float msg0 = deg ? (__fdividef(a0, s0) + EPS) : 0.f;
            float msg1 = deg ? (__fdividef(a1, s1) + EPS) : 0.f;
            float msg2 = deg ? (__fdividef(a2, s2) + EPS) : 0.f;
            float msg3 = deg ? (__fdividef(a3, s3) + EPS) : 0.f;

            float4 own = nf4[node * 16 + l4];
            float ssm = msg0 * msg0 + msg1 * msg1 + msg2 * msg2 + msg3 * msg3;
            float ssf = own.x * own.x + own.y * own.y + own.z * own.z + own.w * own.w;
            #pragma unroll
            for (int o = 8; o; o >>= 1) {            // within 16-lane group: all 64 dims
                ssm += __shfl_xor_sync(0xffffffffu, ssm, o);
                ssf += __shfl_xor_sync(0xffffffffu, ssf, o);
            }
            float coef = sqrtf(ssf) * scale / fmaxf(sqrtf(ssm), 1e-12f);

            if (half == 0) {
                __half2 h0 = __floats2half2_rn(own.x + msg0 * coef, own.y + msg1 * coef);
                __half2 h1 = __floats2half2_rn(own.z + msg2 * coef, own.w + msg3 * coef);
                uint2 o; o.x = *(unsigned*)&h0; o.y = *(unsigned*)&h1;
                g_feat[node * 16 + l4] = o;
            }
        }

        tk = __shfl_sync(0xffffffffu, tk_next, 0);
    }
}

// ---------------- tensor-core GEMM: out = feats @ W + b ----------------------
__global__ void __launch_bounds__(256) k_gemm(
    const float* __restrict__ W, const float* __restrict__ b,
    float* __restrict__ out, int n)
{
    __shared__ __align__(16) __half Ash[128 * 72];   // 128 rows x 64 dims, stride 72
    __shared__ __align__(16) __half Wt[64 * 72];     // Wt[nn*72 + k] = W[k][nn]

    int t = threadIdx.x;
    int R0 = blockIdx.x * 128;

    #pragma unroll
    for (int it = 0; it < 8; it++) {
        int idx = it * 256 + t;
        int row = idx >> 4, l = idx & 15;
        uint2 v = g_feat[(R0 + row) * 16 + l];
        *(uint2*)&Ash[row * 72 + l * 4] = v;
    }
    for (int idx = t; idx < 64 * 64; idx += 256) {
        int k = idx >> 6, nn = idx & 63;
        Wt[nn * 72 + k] = __float2half(W[idx]);
    }
    __syncthreads();

    int w = t >> 5, lane = t & 31;
    int g = lane >> 2, tt = lane & 3;
    int r8 = lane & 7, mq = lane >> 3;
    unsigned ab = (unsigned)__cvta_generic_to_shared(Ash);
    unsigned arow = (unsigned)((w * 16 + (mq & 1) * 8 + r8) * 144 + (mq >> 1) * 16);

    unsigned af[4][4];
    #pragma unroll
    for (int kt = 0; kt < 4; kt++)
        ldsm4(af[kt][0], af[kt][1], af[kt][2], af[kt][3], ab + arow + kt * 32);

    int row0 = R0 + w * 16 + g;
    int row1 = row0 + 8;

    #pragma unroll
    for (int nt = 0; nt < 8; nt++) {
        float2 bb = ((const float2*)b)[nt * 4 + tt];
        float c0 = bb.x, c1 = bb.y, c2 = bb.x, c3 = bb.y;
        #pragma unroll
        for (int kt = 0; kt < 4; kt++) {
            const __half* bp = &Wt[(nt * 8 + g) * 72 + kt * 16 + tt * 2];
            unsigned bf0 = *(const unsigned*)bp;
            unsigned bf1 = *(const unsigned*)(bp + 8);
            mma16816(c0, c1, c2, c3, af[kt][0], af[kt][1], af[kt][2], af[kt][3], bf0, bf1);
        }
        int colb = nt * 8 + tt * 2;
        if (row0 < n) *(float2*)&out[row0 * 64 + colb] = make_float2(c0, c1);
        if (row1 < n) *(float2*)&out[row1 * 64 + colb] = make_float2(c2, c3);
    }
}

extern "C" void kernel_launch(void* const* d_in, const int* in_sizes, int n_in,
                              void* d_out, int out_size) {
    const float* node_feats = (const float*)d_in[0];
    const float* emb0       = (const float*)d_in[1];
    const float* emb1       = (const float*)d_in[2];
    const float* W          = (const float*)d_in[3];
    const float* b          = (const float*)d_in[4];
    const float* beta       = (const float*)d_in[5];
    const float* scale      = (const float*)d_in[6];
    const int*   src        = (const int*)d_in[7];
    const int*   dst        = (const int*)d_in[8];
    const int*   ef0        = (const int*)d_in[9];
    const int*   ef1        = (const int*)d_in[10];

    int n  = in_sizes[0] / 64;
    int e  = in_sizes[7];
    int e8 = e >> 3;

    void* cur_ptr = nullptr;
    cudaGetSymbolAddress(&cur_ptr, g_cur);
    cudaMemsetAsync(cur_ptr, 0, NMAX * sizeof(int));   // degrees + ticket

    k_scatter<<<(e8 + 255) / 256, 256>>>((const int4*)src, (const int4*)dst,
                                         (const int4*)ef0, (const int4*)ef1, e8, e);

    k_main<<<740, 256>>>(node_feats, emb0, emb1, beta, scale, n);

    int gemm_blocks = (n + 127) / 128;
    k_gemm<<<gemm_blocks, 256>>>(W, b, (float*)d_out, n);
}

// round 16
// speedup vs baseline: 1.0966x; 1.0966x over previous
#include <cuda_runtime.h>
#include <cuda_fp16.h>

#define NMAX 50176
#define SLOT 128
#define EPS 1e-7f
#define TICKET (NMAX - 1)

__device__ int g_cur[NMAX];                      // [0,n): degrees; [NMAX-1]: ticket
__device__ unsigned int g_sorted[NMAX * SLOT];   // fixed-slot dst buckets
__device__ __half2 g_nfh[NMAX * 32];             // fp16 shadow of node_feats
__device__ float g_nrm[NMAX];                    // precomputed ||node_feats[i]||
__device__ uint2 g_feat[NMAX * 16];              // fp16 feats (residual output), 4 dims/entry

// ---------------- fused prep: scatter (e4 granularity) + fp16 convert + norms ----
// pack: src in bits [0,17), combo = f0*4+f1 in bits [17,22)
__global__ void k_prep(const int4* __restrict__ src, const int4* __restrict__ dst,
                       const int4* __restrict__ f0, const int4* __restrict__ f1,
                       const float4* __restrict__ nf4,
                       int e4, int e, int scat_blocks, int n16, int n) {
    if ((int)blockIdx.x < scat_blocks) {
        int i = blockIdx.x * blockDim.x + threadIdx.x;
        if (i < e4) {
            int4 s = src[i], d = dst[i], a = f0[i], c = f1[i];
            int p0 = atomicAdd(&g_cur[d.x], 1);
            int p1 = atomicAdd(&g_cur[d.y], 1);
            int p2 = atomicAdd(&g_cur[d.z], 1);
            int p3 = atomicAdd(&g_cur[d.w], 1);
            if (p0 < SLOT) g_sorted[d.x * SLOT + p0] = (unsigned)s.x | ((unsigned)(a.x * 4 + c.x) << 17);
            if (p1 < SLOT) g_sorted[d.y * SLOT + p1] = (unsigned)s.y | ((unsigned)(a.y * 4 + c.y) << 17);
            if (p2 < SLOT) g_sorted[d.z * SLOT + p2] = (unsigned)s.z | ((unsigned)(a.z * 4 + c.z) << 17);
            if (p3 < SLOT) g_sorted[d.w * SLOT + p3] = (unsigned)s.w | ((unsigned)(a.w * 4 + c.w) << 17);
        }
        if (i == 0) {   // tail edges beyond e4*4
            const int* ss = (const int*)src; const int* dd = (const int*)dst;
            const int* aa = (const int*)f0;  const int* cc = (const int*)f1;
            for (int k = e4 * 4; k < e; k++) {
                int p = atomicAdd(&g_cur[dd[k]], 1);
                if (p < SLOT)
                    g_sorted[dd[k] * SLOT + p] = (unsigned)ss[k] | ((unsigned)(aa[k] * 4 + cc[k]) << 17);
            }
        }
    } else {
        // convert + per-node norm (16 consecutive threads = one node)
        int i = ((int)blockIdx.x - scat_blocks) * blockDim.x + threadIdx.x;
        float4 v = make_float4(0.f, 0.f, 0.f, 0.f);
        if (i < n16) {
            v = nf4[i];
            uint2 o;
            __half2 h0 = __floats2half2_rn(v.x, v.y);
            __half2 h1 = __floats2half2_rn(v.z, v.w);
            o.x = *(unsigned*)&h0;
            o.y = *(unsigned*)&h1;
            ((uint2*)g_nfh)[i] = o;
        }
        float ss = v.x * v.x + v.y * v.y + v.z * v.z + v.w * v.w;
        #pragma unroll
        for (int o = 8; o; o >>= 1) ss += __shfl_xor_sync(0xffffffffu, ss, o);
        int node = i >> 4;
        if ((i & 15) == 0 && node < n) g_nrm[node] = sqrtf(ss);
    }
}

__device__ __forceinline__ __half2 u2h(unsigned u) { return *(__half2*)&u; }

__device__ __forceinline__ void ldsm4(unsigned& r0, unsigned& r1, unsigned& r2, unsigned& r3,
                                      unsigned addr) {
    asm volatile("ldmatrix.sync.aligned.m8n8.x4.shared.b16 {%0,%1,%2,%3}, [%4];"
                 : "=r"(r0), "=r"(r1), "=r"(r2), "=r"(r3) : "r"(addr));
}

__device__ __forceinline__ void mma16816(float& c0, float& c1, float& c2, float& c3,
                                         unsigned a0, unsigned a1, unsigned a2, unsigned a3,
                                         unsigned b0, unsigned b1) {
    asm volatile("mma.sync.aligned.m16n8k16.row.col.f32.f16.f16.f32 "
                 "{%0,%1,%2,%3}, {%4,%5,%6,%7}, {%8,%9}, {%0,%1,%2,%3};"
                 : "+f"(c0), "+f"(c1), "+f"(c2), "+f"(c3)
                 : "r"(a0), "r"(a1), "r"(a2), "r"(a3), "r"(b0), "r"(b1));
}

// ---------------- main: per-warp tickets, gather+softmax+MessageNorm+residual ----
__global__ void __launch_bounds__(256) k_main(
    const float* __restrict__ nf,
    const float* __restrict__ emb0, const float* __restrict__ emb1,
    const float* __restrict__ beta_p, const float* __restrict__ scale_p, int n)
{
    __shared__ __align__(16) uint2 etabu[32 * 16];   // 32 combos x 16 uint2 (4 dims each)

    int t = threadIdx.x;
    for (int idx = t; idx < 32 * 16; idx += 256) {
        int c = idx >> 4, l4i = idx & 15;
        int d = 4 * l4i;
        __half2 h0 = __floats2half2_rn(emb0[(c >> 2) * 64 + d]     + emb1[(c & 3) * 64 + d],
                                       emb0[(c >> 2) * 64 + d + 1] + emb1[(c & 3) * 64 + d + 1]);
        __half2 h1 = __floats2half2_rn(emb0[(c >> 2) * 64 + d + 2] + emb1[(c & 3) * 64 + d + 2],
                                       emb0[(c >> 2) * 64 + d + 3] + emb1[(c & 3) * 64 + d + 3]);
        uint2 o; o.x = *(unsigned*)&h0; o.y = *(unsigned*)&h1;
        etabu[idx] = o;
    }
    __syncthreads();

    int lane = t & 31;
    int half = lane >> 4, l4 = lane & 15;
    float bl2f  = beta_p[0] * 1.4426950408889634f;
    float scale = scale_p[0];
    __half2 bl2h = __float2half2_rn(bl2f);
    __half2 negC = __float2half2_rn(-6.0f);          // softmax log2-shift (invariant)
    __half2 zero = __float2half2_rn(0.0f);
    const float4* nf4 = (const float4*)nf;
    const uint2*  nfu = (const uint2*)g_nfh;

    int ntasks = (n + 3) >> 2;                       // 4-node tasks, warp granularity

    for (;;) {
        int tk;
        if (lane == 0) tk = atomicAdd(&g_cur[TICKET], 1);
        tk = __shfl_sync(0xffffffffu, tk, 0);
        if (tk >= ntasks) break;
        int nbase = tk * 4;

        #pragma unroll 1
        for (int q = 0; q < 4; q++) {
            int node = nbase + q;
            if (node >= n) break;
            int deg = g_cur[node];
            deg = deg < SLOT ? deg : SLOT;
            int start = node * SLOT;

            float s0 = 0.f, s1 = 0.f, s2 = 0.f, s3 = 0.f;
            float a0 = 0.f, a1 = 0.f, a2 = 0.f, a3 = 0.f;

            #pragma unroll 1
            for (int base = 0; base < deg; base += 32) {
                int cn = deg - base; if (cn > 32) cn = 32;
                unsigned p = g_sorted[start + base + lane];
                int npair = cn >> 1;
                int gg = 0;
                #pragma unroll 1
                for (; gg + 8 <= npair; gg += 8) {   // 8 pairs = 16 edges per dump
                    __half2 shA = zero, shB = zero, mhA = zero, mhB = zero;
                    #pragma unroll
                    for (int k = 0; k < 8; k++) {
                        unsigned pj = __shfl_sync(0xffffffffu, p, 2 * (gg + k) + half);
                        uint2 xu = nfu[(pj & 0x1FFFFu) * 16 + l4];
                        uint2 eu = etabu[(pj >> 17) * 16 + l4];
                        __half2 m0 = __hmax2(__hadd2(u2h(xu.x), u2h(eu.x)), zero);
                        __half2 m1 = __hmax2(__hadd2(u2h(xu.y), u2h(eu.y)), zero);
                        __half2 w0 = h2exp2(__hfma2(m0, bl2h, negC));
                        __half2 w1 = h2exp2(__hfma2(m1, bl2h, negC));
                        shA = __hadd2(shA, w0); shB = __hadd2(shB, w1);
                        mhA = __hfma2(m0, w0, mhA); mhB = __hfma2(m1, w1, mhB);
                    }
                    float2 fsA = __half22float2(shA), fsB = __half22float2(shB);
                    float2 fmA = __half22float2(mhA), fmB = __half22float2(mhB);
                    s0 += fsA.x; s1 += fsA.y; s2 += fsB.x; s3 += fsB.y;
                    a0 += fmA.x; a1 += fmA.y; a2 += fmB.x; a3 += fmB.y;
                }
                if (gg + 4 <= npair) {             // 4-pair group
                    __half2 shA = zero, shB = zero, mhA = zero, mhB = zero;
                    #pragma unroll
                    for (int k = 0; k < 4; k++) {
                        unsigned pj = __shfl_sync(0xffffffffu, p, 2 * (gg + k) + half);
                        uint2 xu = nfu[(pj & 0x1FFFFu) * 16 + l4];
                        uint2 eu = etabu[(pj >> 17) * 16 + l4];
                        __half2 m0 = __hmax2(__hadd2(u2h(xu.x), u2h(eu.x)), zero);
                        __half2 m1 = __hmax2(__hadd2(u2h(xu.y), u2h(eu.y)), zero);
                        __half2 w0 = h2exp2(__hfma2(m0, bl2h, negC));
                        __half2 w1 = h2exp2(__hfma2(m1, bl2h, negC));
                        shA = __hadd2(shA, w0); shB = __hadd2(shB, w1);
                        mhA = __hfma2(m0, w0, mhA); mhB = __hfma2(m1, w1, mhB);
                    }
                    float2 fsA = __half22float2(shA), fsB = __half22float2(shB);
                    float2 fmA = __half22float2(mhA), fmB = __half22float2(mhB);
                    s0 += fsA.x; s1 += fsA.y; s2 += fsB.x; s3 += fsB.y;
                    a0 += fmA.x; a1 += fmA.y; a2 += fmB.x; a3 += fmB.y;
                    gg += 4;
                }
                #pragma unroll 1
                for (; gg < npair; gg++) {         // leftover pairs
                    unsigned pj = __shfl_sync(0xffffffffu, p, 2 * gg + half);
                    uint2 xu = nfu[(pj & 0x1FFFFu) * 16 + l4];
                    uint2 eu = etabu[(pj >> 17) * 16 + l4];
                    __half2 m0 = __hmax2(__hadd2(u2h(xu.x), u2h(eu.x)), zero);
                    __half2 m1 = __hmax2(__hadd2(u2h(xu.y), u2h(eu.y)), zero);
                    __half2 w0 = h2exp2(__hfma2(m0, bl2h, negC));
                    __half2 w1 = h2exp2(__hfma2(m1, bl2h, negC));
                    float2 fw0 = __half22float2(w0), fw1 = __half22float2(w1);
                    float2 fm0 = __half22float2(__hmul2(m0, w0)), fm1 = __half22float2(__hmul2(m1, w1));
                    s0 += fw0.x; s1 += fw0.y; s2 += fw1.x; s3 += fw1.y;
                    a0 += fm0.x; a1 += fm0.y; a2 += fm1.x; a3 += fm1.y;
                }
                if (cn & 1) {                      // odd tail edge: half 0 only
                    unsigned pj = __shfl_sync(0xffffffffu, p, cn - 1);
                    if (half == 0) {
                        uint2 xu = nfu[(pj & 0x1FFFFu) * 16 + l4];
                        uint2 eu = etabu[(pj >> 17) * 16 + l4];
                        __half2 m0 = __hmax2(__hadd2(u2h(xu.x), u2h(eu.x)), zero);
                        __half2 m1 = __hmax2(__hadd2(u2h(xu.y), u2h(eu.y)), zero);
                        __half2 w0 = h2exp2(__hfma2(m0, bl2h, negC));
                        __half2 w1 = h2exp2(__hfma2(m1, bl2h, negC));
                        float2 fw0 = __half22float2(w0), fw1 = __half22float2(w1);
                        float2 fm0 = __half22float2(__hmul2(m0, w0)), fm1 = __half22float2(__hmul2(m1, w1));
                        s0 += fw0.x; s1 += fw0.y; s2 += fw1.x; s3 += fw1.y;
                        a0 += fm0.x; a1 += fm0.y; a2 += fm1.x; a3 += fm1.y;
                    }
                }
            }

            // fold the two half-warps
            s0 += __shfl_xor_sync(0xffffffffu, s0, 16);
            s1 += __shfl_xor_sync(0xffffffffu, s1, 16);
            s2 += __shfl_xor_sync(0xffffffffu, s2, 16);
            s3 += __shfl_xor_sync(0xffffffffu, s3, 16);
            a0 += __shfl_xor_sync(0xffffffffu, a0, 16);
            a1 += __shfl_xor_sync(0xffffffffu, a1, 16);
            a2 += __shfl_xor_sync(0xffffffffu, a2, 16);
            a3 += __shfl_xor_sync(0xffffffffu, a3, 16);

            float msg0 = deg ? (__fdividef(a0, s0) + EPS) : 0.f;
            float msg1 = deg ? (__fdividef(a1, s1) + EPS) : 0.f;
            float msg2 = deg ? (__fdividef(a2, s2) + EPS) : 0.f;
            float msg3 = deg ? (__fdividef(a3, s3) + EPS) : 0.f;

            float4 own = nf4[node * 16 + l4];
            float nrm = g_nrm[node];
            float ssm = msg0 * msg0 + msg1 * msg1 + msg2 * msg2 + msg3 * msg3;
            #pragma unroll
            for (int o = 8; o; o >>= 1)
                ssm += __shfl_xor_sync(0xffffffffu, ssm, o);
            float coef = nrm * scale / fmaxf(sqrtf(ssm), 1e-12f);

            if (half == 0) {
                __half2 h0 = __floats2half2_rn(own.x + msg0 * coef, own.y + msg1 * coef);
                __half2 h1 = __floats2half2_rn(own.z + msg2 * coef, own.w + msg3 * coef);
                uint2 o; o.x = *(unsigned*)&h0; o.y = *(unsigned*)&h1;
                g_feat[node * 16 + l4] = o;
            }
        }
    }
}

// ---------------- tensor-core GEMM: out = feats @ W + b ----------------------
__global__ void __launch_bounds__(256) k_gemm(
    const float* __restrict__ W, const float* __restrict__ b,
    float* __restrict__ out, int n)
{
    __shared__ __align__(16) __half Ash[128 * 72];   // 128 rows x 64 dims, stride 72
    __shared__ __align__(16) __half Wt[64 * 72];     // Wt[nn*72 + k] = W[k][nn]

    int t = threadIdx.x;
    int R0 = blockIdx.x * 128;

    #pragma unroll
    for (int it = 0; it < 8; it++) {
        int idx = it * 256 + t;
        int row = idx >> 4, l = idx & 15;
        uint2 v = g_feat[(R0 + row) * 16 + l];
        *(uint2*)&Ash[row * 72 + l * 4] = v;
    }
    for (int idx = t; idx < 64 * 64; idx += 256) {
        int k = idx >> 6, nn = idx & 63;
        Wt[nn * 72 + k] = __float2half(W[idx]);
    }
    __syncthreads();

    int w = t >> 5, lane = t & 31;
    int g = lane >> 2, tt = lane & 3;
    int r8 = lane & 7, mq = lane >> 3;
    unsigned ab = (unsigned)__cvta_generic_to_shared(Ash);
    unsigned arow = (unsigned)((w * 16 + (mq & 1) * 8 + r8) * 144 + (mq >> 1) * 16);

    unsigned af[4][4];
    #pragma unroll
    for (int kt = 0; kt < 4; kt++)
        ldsm4(af[kt][0], af[kt][1], af[kt][2], af[kt][3], ab + arow + kt * 32);

    int row0 = R0 + w * 16 + g;
    int row1 = row0 + 8;

    #pragma unroll
    for (int nt = 0; nt < 8; nt++) {
        float2 bb = ((const float2*)b)[nt * 4 + tt];
        float c0 = bb.x, c1 = bb.y, c2 = bb.x, c3 = bb.y;
        #pragma unroll
        for (int kt = 0; kt < 4; kt++) {
            const __half* bp = &Wt[(nt * 8 + g) * 72 + kt * 16 + tt * 2];
            unsigned bf0 = *(const unsigned*)bp;
            unsigned bf1 = *(const unsigned*)(bp + 8);
            mma16816(c0, c1, c2, c3, af[kt][0], af[kt][1], af[kt][2], af[kt][3], bf0, bf1);
        }
        int colb = nt * 8 + tt * 2;
        if (row0 < n) *(float2*)&out[row0 * 64 + colb] = make_float2(c0, c1);
        if (row1 < n) *(float2*)&out[row1 * 64 + colb] = make_float2(c2, c3);
    }
}

extern "C" void kernel_launch(void* const* d_in, const int* in_sizes, int n_in,
                              void* d_out, int out_size) {
    const float* node_feats = (const float*)d_in[0];
    const float* emb0       = (const float*)d_in[1];
    const float* emb1       = (const float*)d_in[2];
    const float* W          = (const float*)d_in[3];
    const float* b          = (const float*)d_in[4];
    const float* beta       = (const float*)d_in[5];
    const float* scale      = (const float*)d_in[6];
    const int*   src        = (const int*)d_in[7];
    const int*   dst        = (const int*)d_in[8];
    const int*   ef0        = (const int*)d_in[9];
    const int*   ef1        = (const int*)d_in[10];

    int n   = in_sizes[0] / 64;
    int n16 = n * 16;
    int e   = in_sizes[7];
    int e4  = e >> 2;

    void* cur_ptr = nullptr;
    cudaGetSymbolAddress(&cur_ptr, g_cur);
    cudaMemsetAsync(cur_ptr, 0, NMAX * sizeof(int));   // degrees + ticket

    int scat_blocks = (e4 + 255) / 256;
    int conv_blocks = (n16 + 255) / 256;
    k_prep<<<scat_blocks + conv_blocks, 256>>>(
        (const int4*)src, (const int4*)dst, (const int4*)ef0, (const int4*)ef1,
        (const float4*)node_feats, e4, e, scat_blocks, n16, n);

    k_main<<<740, 256>>>(node_feats, emb0, emb1, beta, scale, n);

    int gemm_blocks = (n + 127) / 128;
    k_gemm<<<gemm_blocks, 256>>>(W, b, (float*)d_out, n);
}

// round 17
// speedup vs baseline: 1.1239x; 1.0249x over previous
#include <cuda_runtime.h>
#include <cuda_fp16.h>

#define NMAX 50176
#define SLOT 128
#define EPS 1e-7f
#define TICKET (NMAX - 1)

__device__ int g_cur[NMAX];                      // zero-init at load; re-zeroed by k_gemm
__device__ unsigned int g_sorted[NMAX * SLOT];   // fixed-slot dst buckets
__device__ __half2 g_nfh[NMAX * 32];             // fp16 shadow of node_feats
__device__ float g_nrm[NMAX];                    // precomputed ||node_feats[i]||
__device__ uint2 g_feat[NMAX * 16];              // fp16 feats (residual output), 4 dims/entry

// pack: combo=f0*4+f1 in bits [0,5), src<<7 in bits [7,23)  (pre-scaled: src*128 = nf row byte offset)
#define PACK(s, a, c) (((unsigned)(s) << 7) | (unsigned)((a) * 4 + (c)))

// ---------------- fused prep: scatter (e4) + fp16 convert + norms ----------------
__global__ void k_prep(const int4* __restrict__ src, const int4* __restrict__ dst,
                       const int4* __restrict__ f0, const int4* __restrict__ f1,
                       const float4* __restrict__ nf4,
                       int e4, int e, int scat_blocks, int n16, int n) {
    if ((int)blockIdx.x < scat_blocks) {
        int i = blockIdx.x * blockDim.x + threadIdx.x;
        if (i < e4) {
            int4 s = src[i], d = dst[i], a = f0[i], c = f1[i];
            int p0 = atomicAdd(&g_cur[d.x], 1);
            int p1 = atomicAdd(&g_cur[d.y], 1);
            int p2 = atomicAdd(&g_cur[d.z], 1);
            int p3 = atomicAdd(&g_cur[d.w], 1);
            if (p0 < SLOT) g_sorted[d.x * SLOT + p0] = PACK(s.x, a.x, c.x);
            if (p1 < SLOT) g_sorted[d.y * SLOT + p1] = PACK(s.y, a.y, c.y);
            if (p2 < SLOT) g_sorted[d.z * SLOT + p2] = PACK(s.z, a.z, c.z);
            if (p3 < SLOT) g_sorted[d.w * SLOT + p3] = PACK(s.w, a.w, c.w);
        }
        if (i == 0) {   // tail edges beyond e4*4
            const int* ss = (const int*)src; const int* dd = (const int*)dst;
            const int* aa = (const int*)f0;  const int* cc = (const int*)f1;
            for (int k = e4 * 4; k < e; k++) {
                int p = atomicAdd(&g_cur[dd[k]], 1);
                if (p < SLOT)
                    g_sorted[dd[k] * SLOT + p] = PACK(ss[k], aa[k], cc[k]);
            }
        }
    } else {
        // convert + per-node norm (16 consecutive threads = one node)
        int i = ((int)blockIdx.x - scat_blocks) * blockDim.x + threadIdx.x;
        float4 v = make_float4(0.f, 0.f, 0.f, 0.f);
        if (i < n16) {
            v = nf4[i];
            uint2 o;
            __half2 h0 = __floats2half2_rn(v.x, v.y);
            __half2 h1 = __floats2half2_rn(v.z, v.w);
            o.x = *(unsigned*)&h0;
            o.y = *(unsigned*)&h1;
            ((uint2*)g_nfh)[i] = o;
        }
        float ss = v.x * v.x + v.y * v.y + v.z * v.z + v.w * v.w;
        #pragma unroll
        for (int o = 8; o; o >>= 1) ss += __shfl_xor_sync(0xffffffffu, ss, o);
        int node = i >> 4;
        if ((i & 15) == 0 && node < n) g_nrm[node] = sqrtf(ss);
    }
}

__device__ __forceinline__ __half2 u2h(unsigned u) { return *(__half2*)&u; }

__device__ __forceinline__ void ldsm4(unsigned& r0, unsigned& r1, unsigned& r2, unsigned& r3,
                                      unsigned addr) {
    asm volatile("ldmatrix.sync.aligned.m8n8.x4.shared.b16 {%0,%1,%2,%3}, [%4];"
                 : "=r"(r0), "=r"(r1), "=r"(r2), "=r"(r3) : "r"(addr));
}

__device__ __forceinline__ void mma16816(float& c0, float& c1, float& c2, float& c3,
                                         unsigned a0, unsigned a1, unsigned a2, unsigned a3,
                                         unsigned b0, unsigned b1) {
    asm volatile("mma.sync.aligned.m16n8k16.row.col.f32.f16.f16.f32 "
                 "{%0,%1,%2,%3}, {%4,%5,%6,%7}, {%8,%9}, {%0,%1,%2,%3};"
                 : "+f"(c0), "+f"(c1), "+f"(c2), "+f"(c3)
                 : "r"(a0), "r"(a1), "r"(a2), "r"(a3), "r"(b0), "r"(b1));
}

// one edge: nf row via single AND (pre-scaled offset), etab via combo bits [0,5)
#define EDGE_STEP(pj)                                                        \
    do {                                                                     \
        uint2 xu = *(const uint2*)(nfb + ((pj) & 0x7FFF80u));                \
        uint2 eu = etabu[((pj) & 31u) * 16 + l4];                            \
        __half2 m0 = __hmax2(__hadd2(u2h(xu.x), u2h(eu.x)), zero);           \
        __half2 m1 = __hmax2(__hadd2(u2h(xu.y), u2h(eu.y)), zero);           \
        __half2 w0 = h2exp2(__hfma2(m0, bl2h, negC));                        \
        __half2 w1 = h2exp2(__hfma2(m1, bl2h, negC));                        \
        shA = __hadd2(shA, w0); shB = __hadd2(shB, w1);                      \
        mhA = __hfma2(m0, w0, mhA); mhB = __hfma2(m1, w1, mhB);              \
    } while (0)

// ---------------- main: per-warp tickets, gather+softmax+MessageNorm+residual ----
__global__ void __launch_bounds__(256) k_main(
    const float* __restrict__ nf,
    const float* __restrict__ emb0, const float* __restrict__ emb1,
    const float* __restrict__ beta_p, const float* __restrict__ scale_p, int n)
{
    __shared__ __align__(16) uint2 etabu[32 * 16];   // 32 combos x 16 uint2 (4 dims each)

    int t = threadIdx.x;
    for (int idx = t; idx < 32 * 16; idx += 256) {
        int c = idx >> 4, l4i = idx & 15;
        int d = 4 * l4i;
        __half2 h0 = __floats2half2_rn(emb0[(c >> 2) * 64 + d]     + emb1[(c & 3) * 64 + d],
                                       emb0[(c >> 2) * 64 + d + 1] + emb1[(c & 3) * 64 + d + 1]);
        __half2 h1 = __floats2half2_rn(emb0[(c >> 2) * 64 + d + 2] + emb1[(c & 3) * 64 + d + 2],
                                       emb0[(c >> 2) * 64 + d + 3] + emb1[(c & 3) * 64 + d + 3]);
        uint2 o; o.x = *(unsigned*)&h0; o.y = *(unsigned*)&h1;
        etabu[idx] = o;
    }
    __syncthreads();

    int lane = t & 31;
    int half = lane >> 4, l4 = lane & 15;
    float bl2f  = beta_p[0] * 1.4426950408889634f;
    float scale = scale_p[0];
    __half2 bl2h = __float2half2_rn(bl2f);
    __half2 negC = __float2half2_rn(-6.0f);          // softmax log2-shift (invariant)
    __half2 zero = __float2half2_rn(0.0f);
    const float4* nf4 = (const float4*)nf;
    const char*   nfb = (const char*)g_nfh + l4 * 8; // lane-based row pointer

    int ntasks = (n + 3) >> 2;                       // 4-node tasks, warp granularity

    for (;;) {
        int tk;
        if (lane == 0) tk = atomicAdd(&g_cur[TICKET], 1);
        tk = __shfl_sync(0xffffffffu, tk, 0);
        if (tk >= ntasks) break;
        int nbase = tk * 4;

        #pragma unroll 1
        for (int q = 0; q < 4; q++) {
            int node = nbase + q;
            if (node >= n) break;
            int deg = g_cur[node];
            deg = deg < SLOT ? deg : SLOT;
            int start = node * SLOT;

            float s0 = 0.f, s1 = 0.f, s2 = 0.f, s3 = 0.f;
            float a0 = 0.f, a1 = 0.f, a2 = 0.f, a3 = 0.f;

            #pragma unroll 1
            for (int base = 0; base < deg; base += 32) {
                int cn = deg - base; if (cn > 32) cn = 32;
                unsigned p = g_sorted[start + base + lane];
                int npair = cn >> 1;
                int gg = 0;
                #pragma unroll 1
                for (; gg + 8 <= npair; gg += 8) {   // 8 pairs = 16 edges per dump
                    __half2 shA = zero, shB = zero, mhA = zero, mhB = zero;
                    #pragma unroll
                    for (int k = 0; k < 8; k++) {
                        unsigned pj = __shfl_sync(0xffffffffu, p, 2 * (gg + k) + half);
                        EDGE_STEP(pj);
                    }
                    float2 fsA = __half22float2(shA), fsB = __half22float2(shB);
                    float2 fmA = __half22float2(mhA), fmB = __half22float2(mhB);
                    s0 += fsA.x; s1 += fsA.y; s2 += fsB.x; s3 += fsB.y;
                    a0 += fmA.x; a1 += fmA.y; a2 += fmB.x; a3 += fmB.y;
                }
                if (gg + 4 <= npair) {               // 4-pair group
                    __half2 shA = zero, shB = zero, mhA = zero, mhB = zero;
                    #pragma unroll
                    for (int k = 0; k < 4; k++) {
                        unsigned pj = __shfl_sync(0xffffffffu, p, 2 * (gg + k) + half);
                        EDGE_STEP(pj);
                    }
                    float2 fsA = __half22float2(shA), fsB = __half22float2(shB);
                    float2 fmA = __half22float2(mhA), fmB = __half22float2(mhB);
                    s0 += fsA.x; s1 += fsA.y; s2 += fsB.x; s3 += fsB.y;
                    a0 += fmA.x; a1 += fmA.y; a2 += fmB.x; a3 += fmB.y;
                    gg += 4;
                }
                {
                    __half2 shA = zero, shB = zero, mhA = zero, mhB = zero;
                    #pragma unroll 1
                    for (; gg < npair; gg++) {       // leftover pairs
                        unsigned pj = __shfl_sync(0xffffffffu, p, 2 * gg + half);
                        EDGE_STEP(pj);
                    }
                    if (cn & 1) {                    // odd tail edge: half 0 only
                        unsigned pj = __shfl_sync(0xffffffffu, p, cn - 1);
                        if (half == 0) EDGE_STEP(pj);
                    }
                    float2 fsA = __half22float2(shA), fsB = __half22float2(shB);
                    float2 fmA = __half22float2(mhA), fmB = __half22float2(mhB);
                    s0 += fsA.x; s1 += fsA.y; s2 += fsB.x; s3 += fsB.y;
                    a0 += fmA.x; a1 += fmA.y; a2 += fmB.x; a3 += fmB.y;
                }
            }

            // fold the two half-warps
            s0 += __shfl_xor_sync(0xffffffffu, s0, 16);
            s1 += __shfl_xor_sync(0xffffffffu, s1, 16);
            s2 += __shfl_xor_sync(0xffffffffu, s2, 16);
            s3 += __shfl_xor_sync(0xffffffffu, s3, 16);
            a0 += __shfl_xor_sync(0xffffffffu, a0, 16);
            a1 += __shfl_xor_sync(0xffffffffu, a1, 16);
            a2 += __shfl_xor_sync(0xffffffffu, a2, 16);
            a3 += __shfl_xor_sync(0xffffffffu, a3, 16);

            float msg0 = deg ? (__fdividef(a0, s0) + EPS) : 0.f;
            float msg1 = deg ? (__fdividef(a1, s1) + EPS) : 0.f;
            float msg2 = deg ? (__fdividef(a2, s2) + EPS) : 0.f;
            float msg3 = deg ? (__fdividef(a3, s3) + EPS) : 0.f;

            float4 own = nf4[node * 16 + l4];
            float nrm = g_nrm[node];
            float ssm = msg0 * msg0 + msg1 * msg1 + msg2 * msg2 + msg3 * msg3;
            #pragma unroll
            for (int o = 8; o; o >>= 1)
                ssm += __shfl_xor_sync(0xffffffffu, ssm, o);
            float coef = nrm * scale / fmaxf(sqrtf(ssm), 1e-12f);

            if (half == 0) {
                __half2 h0 = __floats2half2_rn(own.x + msg0 * coef, own.y + msg1 * coef);
                __half2 h1 = __floats2half2_rn(own.z + msg2 * coef, own.w + msg3 * coef);
                uint2 o; o.x = *(unsigned*)&h0; o.y = *(unsigned*)&h1;
                g_feat[node * 16 + l4] = o;
            }
        }
    }
}

// ---------------- tensor-core GEMM: out = feats @ W + b; re-zeros g_cur ----------
__global__ void __launch_bounds__(256) k_gemm(
    const float* __restrict__ W, const float* __restrict__ b,
    float* __restrict__ out, int n)
{
    __shared__ __align__(16) __half Ash[128 * 72];   // 128 rows x 64 dims, stride 72
    __shared__ __align__(16) __half Wt[64 * 72];     // Wt[nn*72 + k] = W[k][nn]

    int t = threadIdx.x;
    int R0 = blockIdx.x * 128;

    #pragma unroll
    for (int it = 0; it < 8; it++) {
        int idx = it * 256 + t;
        int row = idx >> 4, l = idx & 15;
        uint2 v = g_feat[(R0 + row) * 16 + l];
        *(uint2*)&Ash[row * 72 + l * 4] = v;
    }
    for (int idx = t; idx < 64 * 64; idx += 256) {
        int k = idx >> 6, nn = idx & 63;
        Wt[nn * 72 + k] = __float2half(W[idx]);
    }

    // re-zero g_cur (degrees + ticket) for the next graph replay.
    // k_main (previous kernel) is complete; no one reads g_cur after this point.
    for (int zi = (int)blockIdx.x * 256 + t; zi < NMAX; zi += (int)gridDim.x * 256)
        g_cur[zi] = 0;

    __syncthreads();

    int w = t >> 5, lane = t & 31;
    int g = lane >> 2, tt = lane & 3;
    int r8 = lane & 7, mq = lane >> 3;
    unsigned ab = (unsigned)__cvta_generic_to_shared(Ash);
    unsigned arow = (unsigned)((w * 16 + (mq & 1) * 8 + r8) * 144 + (mq >> 1) * 16);

    unsigned af[4][4];
    #pragma unroll
    for (int kt = 0; kt < 4; kt++)
        ldsm4(af[kt][0], af[kt][1], af[kt][2], af[kt][3], ab + arow + kt * 32);

    int row0 = R0 + w * 16 + g;
    int row1 = row0 + 8;

    #pragma unroll
    for (int nt = 0; nt < 8; nt++) {
        float2 bb = ((const float2*)b)[nt * 4 + tt];
        float c0 = bb.x, c1 = bb.y, c2 = bb.x, c3 = bb.y;
        #pragma unroll
        for (int kt = 0; kt < 4; kt++) {
            const __half* bp = &Wt[(nt * 8 + g) * 72 + kt * 16 + tt * 2];
            unsigned bf0 = *(const unsigned*)bp;
            unsigned bf1 = *(const unsigned*)(bp + 8);
            mma16816(c0, c1, c2, c3, af[kt][0], af[kt][1], af[kt][2], af[kt][3], bf0, bf1);
        }
        int colb = nt * 8 + tt * 2;
        if (row0 < n) *(float2*)&out[row0 * 64 + colb] = make_float2(c0, c1);
        if (row1 < n) *(float2*)&out[row1 * 64 + colb] = make_float2(c2, c3);
    }
}

extern "C" void kernel_launch(void* const* d_in, const int* in_sizes, int n_in,
                              void* d_out, int out_size) {
    const float* node_feats = (const float*)d_in[0];
    const float* emb0       = (const float*)d_in[1];
    const float* emb1       = (const float*)d_in[2];
    const float* W          = (const float*)d_in[3];
    const float* b          = (const float*)d_in[4];
    const float* beta       = (const float*)d_in[5];
    const float* scale      = (const float*)d_in[6];
    const int*   src        = (const int*)d_in[7];
    const int*   dst        = (const int*)d_in[8];
    const int*   ef0        = (const int*)d_in[9];
    const int*   ef1        = (const int*)d_in[10];

    int n   = in_sizes[0] / 64;
    int n16 = n * 16;
    int e   = in_sizes[7];
    int e4  = e >> 2;

    // g_cur starts zeroed (CUDA zero-init of device globals) and is re-zeroed
    // by k_gemm at the end of every launch, so no memset node is needed.

    int scat_blocks = (e4 + 255) / 256;
    int conv_blocks = (n16 + 255) / 256;
    k_prep<<<scat_blocks + conv_blocks, 256>>>(
        (const int4*)src, (const int4*)dst, (const int4*)ef0, (const int4*)ef1,
        (const float4*)node_feats, e4, e, scat_blocks, n16, n);

    k_main<<<740, 256>>>(node_feats, emb0, emb1, beta, scale, n);

    int gemm_blocks = (n + 127) / 128;
    k_gemm<<<gemm_blocks, 256>>>(W, b, (float*)d_out, n);
}